// round 5
// baseline (speedup 1.0000x reference)
#include <cuda_runtime.h>
#include <math.h>
#include <stdint.h>

#define BATCH 8
#define NTOK  2048
#define FDIM  64
#define ALPHA 0.2f

// ---------------- scratch (__device__ globals; no allocs allowed) ----------
__device__ __align__(16) float g_Wh[BATCH * NTOK * FDIM];     // [b][j][o], tf32-rounded
__device__ __align__(16) float4 g_suv[BATCH * NTOK];          // {sd, e^sd, e^(a*sd), 0}
__device__ float g_ssrc[BATCH * NTOK];
__device__ float g_maxs[BATCH];

__device__ __forceinline__ float eluf(float x) { return x > 0.f ? x : expm1f(x); }

__device__ __forceinline__ uint32_t cvt_tf32(float x) {
    uint32_t r;
    asm("cvt.rna.tf32.f32 %0, %1;" : "=r"(r) : "f"(x));
    return r;
}

__device__ __forceinline__ void mma_tf32(float* d, uint32_t a0, uint32_t a1,
                                         uint32_t a2, uint32_t a3,
                                         uint32_t b0, uint32_t b1) {
    asm volatile(
        "mma.sync.aligned.m16n8k8.row.col.f32.tf32.tf32.f32 "
        "{%0,%1,%2,%3}, {%4,%5,%6,%7}, {%8,%9}, {%0,%1,%2,%3};"
        : "+f"(d[0]), "+f"(d[1]), "+f"(d[2]), "+f"(d[3])
        : "r"(a0), "r"(a1), "r"(a2), "r"(a3), "r"(b0), "r"(b1));
}

// ---------------------------------------------------------------------------
// Kernel 1: Wh = h @ W (stored tf32-rounded), scores, packed suv.
// 256 thr, 64 rows/block, 2 rows/thread; h_s stride 65 (conflict-free).
// ---------------------------------------------------------------------------
__global__ void __launch_bounds__(256) k1_proj(const float* __restrict__ h,
                                               const float* __restrict__ W,
                                               const float* __restrict__ a) {
    __shared__ float W_s[64 * 64];
    __shared__ float a_s[128];
    __shared__ float h_s[64 * 65];

    int tid = threadIdx.x;
    int row0 = blockIdx.x * 64;
    for (int i = tid; i < 4096; i += 256) W_s[i] = W[i];
    if (tid < 128) a_s[tid] = a[tid];
    for (int i = tid; i < 4096; i += 256) h_s[(i >> 6) * 65 + (i & 63)] = h[row0 * 64 + i];
    __syncthreads();

    int rp = tid >> 3, e = tid & 7;      // rows 2rp, 2rp+1; cols e*4 & 32+e*4
    float acc[2][8];
#pragma unroll
    for (int rr = 0; rr < 2; rr++)
#pragma unroll
        for (int i = 0; i < 8; i++) acc[rr][i] = 0.f;

#pragma unroll
    for (int k = 0; k < 64; k++) {
        float4 w0 = *(const float4*)&W_s[k * 64 + e * 4];
        float4 w1 = *(const float4*)&W_s[k * 64 + 32 + e * 4];
#pragma unroll
        for (int rr = 0; rr < 2; rr++) {
            float hv = h_s[(rp * 2 + rr) * 65 + k];
            acc[rr][0] = fmaf(hv, w0.x, acc[rr][0]);
            acc[rr][1] = fmaf(hv, w0.y, acc[rr][1]);
            acc[rr][2] = fmaf(hv, w0.z, acc[rr][2]);
            acc[rr][3] = fmaf(hv, w0.w, acc[rr][3]);
            acc[rr][4] = fmaf(hv, w1.x, acc[rr][4]);
            acc[rr][5] = fmaf(hv, w1.y, acc[rr][5]);
            acc[rr][6] = fmaf(hv, w1.z, acc[rr][6]);
            acc[rr][7] = fmaf(hv, w1.w, acc[rr][7]);
        }
    }

#pragma unroll
    for (int rr = 0; rr < 2; rr++) {
        int row = row0 + rp * 2 + rr;
        // tf32-rounded Wh store (k3's MMA B operand; saves cvt in k3)
        float4 s0, s1;
        s0.x = __uint_as_float(cvt_tf32(acc[rr][0]));
        s0.y = __uint_as_float(cvt_tf32(acc[rr][1]));
        s0.z = __uint_as_float(cvt_tf32(acc[rr][2]));
        s0.w = __uint_as_float(cvt_tf32(acc[rr][3]));
        s1.x = __uint_as_float(cvt_tf32(acc[rr][4]));
        s1.y = __uint_as_float(cvt_tf32(acc[rr][5]));
        s1.z = __uint_as_float(cvt_tf32(acc[rr][6]));
        s1.w = __uint_as_float(cvt_tf32(acc[rr][7]));
        *(float4*)&g_Wh[(size_t)row * 64 + e * 4] = s0;
        *(float4*)&g_Wh[(size_t)row * 64 + 32 + e * 4] = s1;

        float ps = 0.f, pd = 0.f;
#pragma unroll
        for (int i = 0; i < 4; i++) {
            ps = fmaf(acc[rr][i], a_s[e * 4 + i], ps);
            ps = fmaf(acc[rr][i + 4], a_s[32 + e * 4 + i], ps);
            pd = fmaf(acc[rr][i], a_s[64 + e * 4 + i], pd);
            pd = fmaf(acc[rr][i + 4], a_s[96 + e * 4 + i], pd);
        }
#pragma unroll
        for (int o = 1; o < 8; o <<= 1) {
            ps += __shfl_xor_sync(0xffffffffu, ps, o);
            pd += __shfl_xor_sync(0xffffffffu, pd, o);
        }
        if (e == 0) {
            g_ssrc[row] = ps;
            g_suv[row] = make_float4(pd, expf(pd), expf(ALPHA * pd), 0.f);
        }
    }
}

// ---------------------------------------------------------------------------
// Kernel 2: per-batch max of s_dst.  Single block, warp per batch.
// ---------------------------------------------------------------------------
__global__ void __launch_bounds__(256) k2_max() {
    int w = threadIdx.x >> 5, lane = threadIdx.x & 31;
    float m = -1e30f;
    for (int j = lane; j < NTOK; j += 32) m = fmaxf(m, g_suv[w * NTOK + j].x);
#pragma unroll
    for (int o = 16; o > 0; o >>= 1)
        m = fmaxf(m, __shfl_xor_sync(0xffffffffu, m, o));
    if (lane == 0) g_maxs[w] = m;
}

// ---------------------------------------------------------------------------
// Kernel 3: fused attention, mma.sync tf32, double-buffered B tiles.
//   512 thr = 4 m-warps x 4 j-split; warp does 2 m-tiles (32 rows).
//   Z accumulated scalar (no ones-column).  One __syncthreads per tile.
// ---------------------------------------------------------------------------
#define SUV_BYTES  (NTOK * 16)
#define TBYTES     (128 * 72 * 4)
#define SMEM3_TOTAL (SUV_BYTES + 2 * TBYTES)

__global__ void __launch_bounds__(512, 1) k3_attn(float* __restrict__ out) {
    extern __shared__ char smem[];
    float4* suv_s = (float4*)smem;
    float*  Tb[2] = { (float*)(smem + SUV_BYTES),
                      (float*)(smem + SUV_BYTES + TBYTES) };

    int tid = threadIdx.x;
    int lane = tid & 31;
    int wid = tid >> 5;
    int mw = wid & 3, js = wid >> 2;
    int b = blockIdx.y;
    int i0 = blockIdx.x * 128;

    {
        const float4* sg = g_suv + b * NTOK;
        for (int i = tid; i < NTOK; i += 512) suv_s[i] = sg[i];
    }

    int q = lane >> 2, c4 = lane & 3;
    int rbase = i0 + mw * 32 + q;
    float M = g_maxs[b];
    float ssr[4], Ai[4], Bi[4];
#pragma unroll
    for (int rr = 0; rr < 4; rr++) {
        float s = g_ssrc[b * NTOK + rbase + rr * 8];
        float t = s + M;
        float m = t > 0.f ? t : ALPHA * t;
        ssr[rr] = s;
        Ai[rr] = expf(s - m);
        Bi[rr] = expf(ALPHA * s - m);
    }

    float acc[2][8][4];
    float z[4] = {0.f, 0.f, 0.f, 0.f};
#pragma unroll
    for (int mt = 0; mt < 2; mt++)
#pragma unroll
        for (int n = 0; n < 8; n++)
#pragma unroll
            for (int i = 0; i < 4; i++) acc[mt][n][i] = 0.f;

    const float4* WhG4 = (const float4*)(g_Wh + (size_t)b * NTOK * 64);
    int sj = tid >> 4, so4 = tid & 15;     // staging: j-row, o-quad (it adds 32 j)

    // stage tile 0 into buf 0 (Wh already tf32-rounded)
#pragma unroll
    for (int it = 0; it < 4; it++) {
        float4 v = WhG4[(size_t)(sj + it * 32) * 16 + so4];
        *(float4*)&Tb[0][(sj + it * 32) * 72 + so4 * 4] = v;
    }
    __syncthreads();

    for (int t = 0; t < 16; t++) {
        const float* cur = Tb[t & 1];
        float* nxt = Tb[(t + 1) & 1];
        float4 pf[4];
        if (t < 15) {
#pragma unroll
            for (int it = 0; it < 4; it++)
                pf[it] = WhG4[(size_t)((t + 1) * 128 + sj + it * 32) * 16 + so4];
        }

#pragma unroll
        for (int cc = 0; cc < 4; cc++) {
            int c = js * 4 + cc;
            int jb = t * 128 + c * 8;
            float4 s0 = suv_s[jb + c4];
            float4 s1 = suv_s[jb + 4 + c4];
            uint32_t af[2][4];
#pragma unroll
            for (int mt = 0; mt < 2; mt++) {
                int r0 = mt * 2, r1 = mt * 2 + 1;
                float p0 = (ssr[r0] + s0.x > 0.f) ? Ai[r0] * s0.y : Bi[r0] * s0.z;
                float p1 = (ssr[r1] + s0.x > 0.f) ? Ai[r1] * s0.y : Bi[r1] * s0.z;
                float p2 = (ssr[r0] + s1.x > 0.f) ? Ai[r0] * s1.y : Bi[r0] * s1.z;
                float p3 = (ssr[r1] + s1.x > 0.f) ? Ai[r1] * s1.y : Bi[r1] * s1.z;
                z[r0] += p0 + p2;
                z[r1] += p1 + p3;
                af[mt][0] = cvt_tf32(p0);
                af[mt][1] = cvt_tf32(p1);
                af[mt][2] = cvt_tf32(p2);
                af[mt][3] = cvt_tf32(p3);
            }
            const float* bp = cur + (c * 8 + c4) * 72 + q;
#pragma unroll
            for (int n = 0; n < 8; n++) {
                uint32_t b0 = __float_as_uint(bp[n * 8]);
                uint32_t b1 = __float_as_uint(bp[4 * 72 + n * 8]);
                mma_tf32(acc[0][n], af[0][0], af[0][1], af[0][2], af[0][3], b0, b1);
                mma_tf32(acc[1][n], af[1][0], af[1][1], af[1][2], af[1][3], b0, b1);
            }
        }

        if (t < 15) {
#pragma unroll
            for (int it = 0; it < 4; it++)
                *(float4*)&nxt[(sj + it * 32) * 72 + so4 * 4] = pf[it];
        }
        __syncthreads();
    }

    // ---- reduce across js groups: payload = 64 acc + 4 z (stride 69) ----
    float* red = Tb[0];
    int slot = tid & 127;
    float* accf = &acc[0][0][0];
#pragma unroll
    for (int src = 1; src < 4; src++) {
        if (js == src) {
#pragma unroll
            for (int i = 0; i < 64; i++) red[slot * 69 + i] = accf[i];
#pragma unroll
            for (int i = 0; i < 4; i++) red[slot * 69 + 64 + i] = z[i];
        }
        __syncthreads();
        if (js == 0) {
#pragma unroll
            for (int i = 0; i < 64; i++) accf[i] += red[slot * 69 + i];
#pragma unroll
            for (int i = 0; i < 4; i++) z[i] += red[slot * 69 + 64 + i];
        }
        __syncthreads();
    }

    // ---- epilogue (js == 0) ----
    if (js == 0) {
        // finish Z: sum over the c4 quad (j-coverage {c4, 4+c4} per lane)
#pragma unroll
        for (int rr = 0; rr < 4; rr++) {
            z[rr] += __shfl_xor_sync(0xffffffffu, z[rr], 1);
            z[rr] += __shfl_xor_sync(0xffffffffu, z[rr], 2);
        }
        float inv0 = 1.f / z[0], inv1 = 1.f / z[1];
        float inv2 = 1.f / z[2], inv3 = 1.f / z[3];

        float* o0 = out + ((size_t)(b * NTOK + rbase)) * 64 + 2 * c4;
        float* o1 = o0 + 8 * 64;
        float* o2 = o0 + 16 * 64;
        float* o3 = o0 + 24 * 64;
#pragma unroll
        for (int n = 0; n < 8; n++) {
            float2 w0, w1, w2, w3;
            w0.x = eluf(acc[0][n][0] * inv0);
            w0.y = eluf(acc[0][n][1] * inv0);
            w1.x = eluf(acc[0][n][2] * inv1);
            w1.y = eluf(acc[0][n][3] * inv1);
            w2.x = eluf(acc[1][n][0] * inv2);
            w2.y = eluf(acc[1][n][1] * inv2);
            w3.x = eluf(acc[1][n][2] * inv3);
            w3.y = eluf(acc[1][n][3] * inv3);
            *(float2*)(o0 + n * 8) = w0;
            *(float2*)(o1 + n * 8) = w1;
            *(float2*)(o2 + n * 8) = w2;
            *(float2*)(o3 + n * 8) = w3;
        }
    }
}

// ---------------------------------------------------------------------------
extern "C" void kernel_launch(void* const* d_in, const int* in_sizes, int n_in,
                              void* d_out, int out_size) {
    const float* h = (const float*)d_in[0];
    const float* W = (const float*)d_in[1];
    const float* a = (const float*)d_in[2];
    float* out = (float*)d_out;

    cudaFuncSetAttribute(k3_attn, cudaFuncAttributeMaxDynamicSharedMemorySize,
                         SMEM3_TOTAL);

    k1_proj<<<(BATCH * NTOK) / 64, 256>>>(h, W, a);
    k2_max<<<1, 256>>>();
    dim3 g3(NTOK / 128, BATCH);
    k3_attn<<<g3, 512, SMEM3_TOTAL>>>(out);
}